// round 9
// baseline (speedup 1.0000x reference)
#include <cuda_runtime.h>
#include <cstdint>
#include <math.h>

#define BATCH 64
#define SEQ   2048
#define INP   256
#define HID   512
#define NCTA  128
#define CLU   8      // CTAs per cluster = one batch group
#define BGR   4      // batches per CTA
#define JGR   64     // hidden columns per CTA
#define USTR  516    // padded U row stride (floats); 516*4=2064B keeps 16B align

// ---------------- scratch (no allocations allowed) ----------------
__device__ float g_wx[(size_t)BATCH * SEQ * HID];   // 268 MB precomputed input projections
__device__ float g_hbuf[BATCH * HID];               // final hidden state for phase 3

// ---------------- packed fp32x2 FMA helpers (FFMA2) ----------------
__device__ __forceinline__ void fma2(unsigned long long &d, unsigned long long a, unsigned long long b) {
    asm("fma.rn.f32x2 %0, %1, %2, %0;" : "+l"(d) : "l"(a), "l"(b));
}
__device__ __forceinline__ unsigned long long pack2(float lo, float hi) {
    unsigned long long r;
    asm("mov.b64 %0, {%1, %2};" : "=l"(r) : "f"(lo), "f"(hi));
    return r;
}
__device__ __forceinline__ float lo2(unsigned long long v) { return __uint_as_float((unsigned)v); }
__device__ __forceinline__ float hi2(unsigned long long v) { return __uint_as_float((unsigned)(v >> 32)); }

// ---------------- cluster / DSMEM helpers ----------------
__device__ __forceinline__ uint32_t smem_u32(const void* p) {
    uint32_t a;
    asm("{ .reg .u64 t; cvta.to.shared.u64 t, %1; cvt.u32.u64 %0, t; }" : "=r"(a) : "l"(p));
    return a;
}
__device__ __forceinline__ uint32_t my_cluster_rank() {
    uint32_t r; asm("mov.u32 %0, %%cluster_ctarank;" : "=r"(r)); return r;
}
__device__ __forceinline__ uint32_t mapa_u32(uint32_t laddr, uint32_t rank) {
    uint32_t r;
    asm("mapa.shared::cluster.u32 %0, %1, %2;" : "=r"(r) : "r"(laddr), "r"(rank));
    return r;
}
__device__ __forceinline__ float4 ld_cluster_f4(uint32_t a) {
    float4 v;
    asm volatile("ld.shared::cluster.v4.f32 {%0,%1,%2,%3}, [%4];"
                 : "=f"(v.x), "=f"(v.y), "=f"(v.z), "=f"(v.w) : "r"(a));
    return v;
}
__device__ __forceinline__ void mbar_init(uint32_t a, uint32_t cnt) {
    asm volatile("mbarrier.init.shared.b64 [%0], %1;" :: "r"(a), "r"(cnt) : "memory");
}
__device__ __forceinline__ void mbar_arrive_cluster(uint32_t remaddr) {
    asm volatile("mbarrier.arrive.release.cluster.shared::cluster.b64 _, [%0];"
                 :: "r"(remaddr) : "memory");
}
#define MBAR_WAIT_CLUSTER(mb, ph) do {                                               \
    uint32_t _d;                                                                     \
    asm volatile("{\n\t.reg .pred p;\n\t"                                            \
        "mbarrier.try_wait.parity.acquire.cluster.shared::cta.b64 p, [%1], %2, 0x989680;\n\t" \
        "selp.b32 %0,1,0,p;\n\t}" : "=r"(_d) : "r"(mb), "r"(ph) : "memory");         \
    while (!_d) {                                                                    \
        asm volatile("{\n\t.reg .pred p;\n\t"                                        \
            "mbarrier.try_wait.parity.acquire.cluster.shared::cta.b64 p, [%1], %2, 0x989680;\n\t" \
            "selp.b32 %0,1,0,p;\n\t}" : "=r"(_d) : "r"(mb), "r"(ph) : "memory");     \
    }                                                                                \
} while (0)
#define CLUSTER_SYNC() do {                                          \
    asm volatile("barrier.cluster.arrive.aligned;" ::: "memory");    \
    asm volatile("barrier.cluster.wait.aligned;" ::: "memory");      \
} while (0)

// dynamic smem layout (identical in every CTA of the cluster -> mapa-safe)
#define SM_MBAR   0
#define SM_HTILE  16                         // float htile[2][256]  (2 KB)
#define SM_HSH    (SM_HTILE + 2048)          // float hsh[4][512]    (8 KB)
#define SM_USH    (SM_HSH + 4 * HID * 4)     // float Ush[64][USTR]  (132,096 B)
#define SM_TOTAL  (SM_USH + JGR * USTR * 4)

// =====================================================================
// Phase 1: wx[b,s,:] = x[b,s,:] @ W + Wb      (M=131072, N=512, K=256)
// (~820us; revisit if it becomes the bottleneck)
// =====================================================================
#define P1_BM 64
#define P1_BN 64
#define P1_BK 64

__global__ __launch_bounds__(256) void wx_kernel(const float* __restrict__ X,
                                                 const float* __restrict__ W,
                                                 const float* __restrict__ Wb) {
    __shared__ float Xs[P1_BM][P1_BK + 4];
    __shared__ float Ws[P1_BK][P1_BN + 4];

    const int t    = threadIdx.x;
    const int mpos = t >> 4;
    const int npos = t & 15;
    const int m0   = blockIdx.x * P1_BM;
    const int n0   = blockIdx.y * P1_BN;

    unsigned long long acc[4][2];
#pragma unroll
    for (int i = 0; i < 4; i++) { acc[i][0] = 0ull; acc[i][1] = 0ull; }

    for (int k0 = 0; k0 < INP; k0 += P1_BK) {
#pragma unroll
        for (int i = t; i < (P1_BM * P1_BK) / 4; i += 256) {
            int r = i >> 4;
            int c = i & 15;
            float4 v = *(const float4*)(X + (size_t)(m0 + r) * INP + k0 + c * 4);
            *(float4*)(&Xs[r][c * 4]) = v;
        }
#pragma unroll
        for (int i = t; i < (P1_BK * P1_BN) / 4; i += 256) {
            int r = i >> 4;
            int c = i & 15;
            float4 v = *(const float4*)(W + (size_t)(k0 + r) * HID + n0 + c * 4);
            *(float4*)(&Ws[r][c * 4]) = v;
        }
        __syncthreads();

#pragma unroll
        for (int k = 0; k < P1_BK; k++) {
            ulonglong2 w = *(const ulonglong2*)(&Ws[k][npos * 4]);
#pragma unroll
            for (int i = 0; i < 4; i++) {
                float a = Xs[mpos * 4 + i][k];
                unsigned long long ad = pack2(a, a);
                fma2(acc[i][0], ad, w.x);
                fma2(acc[i][1], ad, w.y);
            }
        }
        __syncthreads();
    }

    float4 bb = *(const float4*)(Wb + n0 + npos * 4);
#pragma unroll
    for (int i = 0; i < 4; i++) {
        float4 v;
        v.x = lo2(acc[i][0]) + bb.x;
        v.y = hi2(acc[i][0]) + bb.y;
        v.z = lo2(acc[i][1]) + bb.z;
        v.w = hi2(acc[i][1]) + bb.w;
        *(float4*)(g_wx + (size_t)(m0 + mpos * 4 + i) * HID + n0 + npos * 4) = v;
    }
}

// =====================================================================
// Phase 2: persistent RNN scan — clusters of 8 CTAs, DSMEM h-exchange.
// CTA (bg, rank) = 4 batches x 64 cols, 512 threads (16 warps, 4/SMSP).
// h tile (1KB, double-buffered) lives in OWN smem; each step, peers pull
// 8KB of h via ld.shared::cluster after an mbarrier (8 arrivals) handshake.
// Correctness under arrival reordering: data for h(s) is written to
// htile[s&1] BEFORE any s-announcement; overwrite of a buffer happens 2
// steps later, gated by arrivals that happen-after all pulls of it.
// Compute: warp tile 4b x 4j, full K split over 32 lanes in 4 quads
// (warp-wide LDS.128 = contiguous conflict-free 512B); 4-stage butterfly
// + one xor-1 fold; lane L holds output (L>>1); even lanes write.
// =====================================================================
__global__ __launch_bounds__(512, 1) __cluster_dims__(CLU, 1, 1)
void rnn_kernel(const float* __restrict__ Uw, const float* __restrict__ Ub) {
    extern __shared__ char smc[];
    float* htile = (float*)(smc + SM_HTILE);   // [2][256]
    float* hsh   = (float*)(smc + SM_HSH);     // [4][512]
    float* Ush   = (float*)(smc + SM_USH);     // [64][USTR]

    const uint32_t smb   = smem_u32(smc);
    const uint32_t mbar  = smb + SM_MBAR;
    const int t    = threadIdx.x;
    const int w    = t >> 5;
    const int lane = t & 31;
    const uint32_t rank = my_cluster_rank();
    const int bg   = blockIdx.x >> 3;          // 16 batch groups
    const int b0   = bg * BGR;
    const int j0   = (int)rank * JGR;

    // output mapping (after butterfly): o=(lane>>1)&15 -> b=o>>2, jl=o&3
    const int ob  = (lane >> 3) & 3;
    const int ojl = (lane >> 1) & 3;
    const int jglob = j0 + w * 4 + ojl;
    const bool writer = ((lane & 1) == 0);

    // mbarrier init + cluster-wide visibility before any arrival
    if (t == 0) mbar_init(mbar, CLU);
    __syncthreads();
    CLUSTER_SYNC();

    // one-time: U slice transposed -> Ush[j][k] = U[k][j0+j]
    for (int i = t; i < JGR * HID; i += 512) {
        int jj = i & 63;
        int k  = i >> 6;
        Ush[jj * USTR + k] = Uw[(size_t)k * HID + j0 + jj];
    }
    const float ubj = writer ? Ub[jglob] : 0.0f;
    const float* wxp = g_wx + (size_t)(b0 + ob) * SEQ * HID + jglob;

    // per-thread pull descriptor: thread t pulls one float4 of hsh
    const int pb  = t >> 7;          // batch row 0..3
    const int pc4 = t & 127;         // float4 column 0..127
    const int pr  = pc4 >> 4;        // source rank
    const int pj4 = pc4 & 15;        // float4 within source tile row
    const uint32_t pull_src0 = mapa_u32(smb + SM_HTILE + (uint32_t)(pb * 256 + pj4 * 16), pr);
    float* const pull_dst = hsh + pb * HID + pc4 * 4;

    // per-thread arrival target (t < 8)
    const uint32_t peer_mbar = (t < CLU) ? mapa_u32(mbar, (uint32_t)t) : 0u;

    __syncthreads();

    uint32_t ph = 0;
    for (int s = 0; s < SEQ; s++) {
        // issue wx load early (writers only); consumed ~2000+ cycles later
        float wxv = 0.0f;
        if (writer) wxv = wxp[(size_t)s * HID];

        if (s == 0) {
            *(float4*)(hsh + t * 4) = make_float4(0.f, 0.f, 0.f, 0.f);
        } else {
            MBAR_WAIT_CLUSTER(mbar, ph);
            ph ^= 1;
            // pull h(s) from all 8 peers' htile[s&1] (8KB total, 1 f4/thread)
            float4 hv = ld_cluster_f4(pull_src0 + (uint32_t)((s & 1) << 10));
            *(float4*)pull_dst = hv;
        }
        __syncthreads();

        // 4b x 4j register tile, full K split over lanes in 4 quads
        unsigned long long acc[16];
#pragma unroll
        for (int o = 0; o < 16; o++) acc[o] = 0ull;

#pragma unroll
        for (int qi = 0; qi < 4; qi++) {
            const int kb = qi * 128 + lane * 4;
            ulonglong2 hq[4], uq[4];
#pragma unroll
            for (int b = 0; b < 4; b++)
                hq[b] = *(const ulonglong2*)(hsh + b * HID + kb);
#pragma unroll
            for (int j = 0; j < 4; j++)
                uq[j] = *(const ulonglong2*)(Ush + (w * 4 + j) * USTR + kb);
#pragma unroll
            for (int b = 0; b < 4; b++)
#pragma unroll
                for (int j = 0; j < 4; j++) {
                    fma2(acc[b * 4 + j], hq[b].x, uq[j].x);
                    fma2(acc[b * 4 + j], hq[b].y, uq[j].y);
                }
        }

        float v[16];
#pragma unroll
        for (int o = 0; o < 16; o++) v[o] = lo2(acc[o]) + hi2(acc[o]);

#define BFLY_STAGE(OFF, NKEEP)                                              \
        do {                                                                \
            const bool up = (lane & (OFF)) != 0;                            \
            _Pragma("unroll")                                               \
            for (int i = 0; i < (NKEEP); i++) {                             \
                float send = up ? v[i] : v[i + (NKEEP)];                    \
                float recv = __shfl_xor_sync(0xffffffffu, send, (OFF));     \
                v[i] = (up ? v[i + (NKEEP)] : v[i]) + recv;                 \
            }                                                               \
        } while (0)

        BFLY_STAGE(16, 8);
        BFLY_STAGE(8, 4);
        BFLY_STAGE(4, 2);
        BFLY_STAGE(2, 1);
#undef BFLY_STAGE
        v[0] += __shfl_xor_sync(0xffffffffu, v[0], 1);   // fold k-parity pair

        if (writer) {
            float hnew = tanhf(wxv + ubj + v[0]);
            htile[((s + 1) & 1) * 256 + ob * 64 + w * 4 + ojl] = hnew;
            if (s == SEQ - 1)
                g_hbuf[(size_t)(b0 + ob) * HID + jglob] = hnew;
        }

        // tile complete before announcing h(s+1) to all ranks (incl. self)
        __syncthreads();
        if (t < CLU) mbar_arrive_cluster(peer_mbar);
    }

    // no CTA may exit while peers might still read its smem / mbar
    CLUSTER_SYNC();
}

// =====================================================================
// Phase 3: out = sigmoid(h_T @ V + Vb)
// =====================================================================
__global__ __launch_bounds__(128) void out_kernel(const float* __restrict__ Vw,
                                                  const float* __restrict__ Vb,
                                                  float* __restrict__ out) {
    const int bb = blockIdx.x;
    const int t  = threadIdx.x;
    const float* h = g_hbuf + (size_t)bb * HID;

    float a0 = 0.f, a1 = 0.f;
    for (int k = t; k < HID; k += 128) {
        float hv = h[k];
        a0 += hv * Vw[k * 2 + 0];
        a1 += hv * Vw[k * 2 + 1];
    }
#pragma unroll
    for (int off = 16; off > 0; off >>= 1) {
        a0 += __shfl_down_sync(0xffffffffu, a0, off);
        a1 += __shfl_down_sync(0xffffffffu, a1, off);
    }
    __shared__ float p0[4], p1[4];
    if ((t & 31) == 0) { p0[t >> 5] = a0; p1[t >> 5] = a1; }
    __syncthreads();
    if (t == 0) {
        float s0 = p0[0] + p0[1] + p0[2] + p0[3] + Vb[0];
        float s1 = p1[0] + p1[1] + p1[2] + p1[3] + Vb[1];
        out[bb * 2 + 0] = 1.f / (1.f + expf(-s0));
        out[bb * 2 + 1] = 1.f / (1.f + expf(-s1));
    }
}

// =====================================================================
extern "C" void kernel_launch(void* const* d_in, const int* in_sizes, int n_in,
                              void* d_out, int out_size) {
    const float* x  = (const float*)d_in[0];
    const float* Ww = (const float*)d_in[1];
    const float* Wb = (const float*)d_in[2];
    const float* Uw = (const float*)d_in[3];
    const float* Ub = (const float*)d_in[4];
    const float* Vw = (const float*)d_in[5];
    const float* Vb = (const float*)d_in[6];
    float* out = (float*)d_out;

    // Phase 1: input projections for all timesteps
    dim3 g1((BATCH * SEQ) / P1_BM, HID / P1_BN);
    wx_kernel<<<g1, 256>>>(x, Ww, Wb);

    // Phase 2: persistent clustered scan (~139 KB dynamic smem)
    cudaFuncSetAttribute(rnn_kernel, cudaFuncAttributeMaxDynamicSharedMemorySize, SM_TOTAL);
    rnn_kernel<<<NCTA, 512, SM_TOTAL>>>(Uw, Ub);

    // Phase 3: readout
    out_kernel<<<BATCH, 128>>>(Vw, Vb, out);
}